// round 11
// baseline (speedup 1.0000x reference)
#include <cuda_runtime.h>
#include <cuda_bf16.h>
#include <math.h>

#define BB 4
#define LL 4096
#define DD 256
#define AA 64
#define NROWS (BB*LL)
#define NPAIR 32           // 64 elems -> 32 bf16x2 pairs
#define DPAIR 128          // 256 dims -> 128 pairs
#define TSTRIDE 36         // smem tile row stride (u32): 144B rows, ldmatrix conflict-free
#define NCH 4              // max chunks per 128-row query tile
#define CHT 16             // key-tiles per chunk
#define NQT 32             // 128-row query tiles per batch
#define LOG2E 1.4426950408889634f

// Packed bf16 hi/lo splits
__device__ unsigned g_qhi[NROWS*NPAIR], g_qlo[NROWS*NPAIR];
__device__ unsigned g_khi[NROWS*NPAIR], g_klo[NROWS*NPAIR];
__device__ unsigned g_vthi[BB*AA*(LL/2)], g_vtlo[BB*AA*(LL/2)];  // [b][d][keypair]
__device__ unsigned g_wtp_hi[3*AA*DPAIR], g_wtp_lo[3*AA*DPAIR];  // [mat][a][dpair]
// Split-KV partials: slot = (b*NQT+qt2)*NCH+chunk, 128 rows x 64 cols
__device__ float g_pO[BB*NQT*NCH*128*64];
__device__ float g_pm[BB*NQT*NCH*128];   // log2 domain
__device__ float g_pl[BB*NQT*NCH*128];

// ---------------------------------------------------------------------------
__device__ __forceinline__ void split2(float f0, float f1, unsigned &hi, unsigned &lo) {
    unsigned u0 = __float_as_uint(f0), u1 = __float_as_uint(f1);
    hi = __byte_perm(u0, u1, 0x7632);                       // {u1.hi16, u0.hi16}
    float r0 = f0 - __uint_as_float(u0 & 0xffff0000u);      // exact
    float r1 = f1 - __uint_as_float(u1 & 0xffff0000u);      // exact
    __nv_bfloat162 p = __floats2bfloat162_rn(r0, r1);
    lo = *(unsigned*)&p;
}

__device__ __forceinline__ float ex2(float x) {
    float y;
    asm("ex2.approx.ftz.f32 %0, %1;" : "=f"(y) : "f"(x));
    return y;
}

__device__ __forceinline__ void mma_bf16(float (&d)[4], const unsigned (&a)[4],
                                         unsigned b0, unsigned b1) {
    asm volatile(
        "mma.sync.aligned.m16n8k16.row.col.f32.bf16.bf16.f32 "
        "{%0,%1,%2,%3}, {%4,%5,%6,%7}, {%8,%9}, {%0,%1,%2,%3};"
        : "+f"(d[0]), "+f"(d[1]), "+f"(d[2]), "+f"(d[3])
        : "r"(a[0]), "r"(a[1]), "r"(a[2]), "r"(a[3]), "r"(b0), "r"(b1));
}

__device__ __forceinline__ void ldm_x4(unsigned &r0, unsigned &r1,
                                       unsigned &r2, unsigned &r3, unsigned addr) {
    asm volatile("ldmatrix.sync.aligned.m8n8.x4.shared.b16 {%0,%1,%2,%3}, [%4];"
                 : "=r"(r0), "=r"(r1), "=r"(r2), "=r"(r3) : "r"(addr));
}

__device__ __forceinline__ void cpa16(void* s, const void* g) {
    unsigned sa = (unsigned)__cvta_generic_to_shared(s);
    asm volatile("cp.async.cg.shared.global [%0], [%1], 16;" :: "r"(sa), "l"(g));
}

// B-fragment lane offset (u32 units)
__device__ __forceinline__ unsigned bfrag_off(int lane) {
    return ((lane >> 4) * 8 * TSTRIDE + (lane & 7) * TSTRIDE + ((lane >> 3) & 1) * 4);
}
// A-fragment lane offset (u32 units)
__device__ __forceinline__ unsigned afrag_off(int lane) {
    return (((lane & 7) + ((lane >> 3) & 1) * 8) * TSTRIDE + (lane >> 4) * 4);
}

// ---------------------------------------------------------------------------
// Kernel 0: split W into packed [mat][a][dpair] hi/lo (tiny).
// ---------------------------------------------------------------------------
__global__ void prepw_kernel(const float* __restrict__ Wq,
                             const float* __restrict__ Wk,
                             const float* __restrict__ Wv) {
    const int total = 3 * AA * DPAIR;
    for (int i = blockIdx.x * blockDim.x + threadIdx.x; i < total;
         i += gridDim.x * blockDim.x) {
        int m = i / (AA * DPAIR);
        int r = i % (AA * DPAIR);
        int a = r >> 7, p = r & 127;
        const float* W = (m == 0) ? Wq : (m == 1) ? Wk : Wv;
        float w0 = W[(size_t)(2*p)   * AA + a];
        float w1 = W[(size_t)(2*p+1) * AA + a];
        split2(w0, w1, g_wtp_hi[i], g_wtp_lo[i]);
    }
}

// ---------------------------------------------------------------------------
// Kernel 1: QKV projection on tensor cores (unchanged).
// grid = (3, NROWS/64), block = 128.
// ---------------------------------------------------------------------------
__global__ __launch_bounds__(128)
void qkv_kernel(const float* __restrict__ x) {
    __shared__ unsigned xs_hi[64*TSTRIDE], xs_lo[64*TSTRIDE];
    __shared__ unsigned ws_hi[64*TSTRIDE], ws_lo[64*TSTRIDE];

    const int mat  = blockIdx.x;
    const int row0 = blockIdx.y * 64;
    const int tid  = threadIdx.x;
    const int wid  = tid >> 5;
    const int lane = tid & 31;
    const int g    = lane >> 2;
    const int tig  = lane & 3;
    const int g0   = wid * 16;

    const unsigned xh_b = (unsigned)__cvta_generic_to_shared(xs_hi);
    const unsigned xl_b = (unsigned)__cvta_generic_to_shared(xs_lo);
    const unsigned wh_b = (unsigned)__cvta_generic_to_shared(ws_hi);
    const unsigned wl_b = (unsigned)__cvta_generic_to_shared(ws_lo);
    const unsigned aoff = (g0 * TSTRIDE + afrag_off(lane)) * 4;
    const unsigned boff = bfrag_off(lane) * 4;

    float o[8][4] = {};

    for (int d0 = 0; d0 < DD; d0 += 64) {
        __syncthreads();
        {
            const int r = tid >> 1;
            const int p0 = (tid & 1) * 16;
            const float* src = x + (size_t)(row0 + r) * DD + d0 + p0 * 2;
            unsigned* dh = &xs_hi[r * TSTRIDE + p0];
            unsigned* dl = &xs_lo[r * TSTRIDE + p0];
            #pragma unroll
            for (int i = 0; i < 8; ++i) {
                float4 f = *(const float4*)(src + 4*i);
                split2(f.x, f.y, dh[2*i],   dl[2*i]);
                split2(f.z, f.w, dh[2*i+1], dl[2*i+1]);
            }
        }
        {
            const int a  = tid >> 1;
            const int p0 = (tid & 1) * 16;
            const uint4* sh = (const uint4*)&g_wtp_hi[(size_t)mat*AA*DPAIR + a*DPAIR + (d0>>1) + p0];
            const uint4* sl = (const uint4*)&g_wtp_lo[(size_t)mat*AA*DPAIR + a*DPAIR + (d0>>1) + p0];
            uint4* dh = (uint4*)&ws_hi[a * TSTRIDE + p0];
            uint4* dl = (uint4*)&ws_lo[a * TSTRIDE + p0];
            #pragma unroll
            for (int i = 0; i < 4; ++i) { dh[i] = sh[i]; dl[i] = sl[i]; }
        }
        __syncthreads();

        #pragma unroll
        for (int ks = 0; ks < 4; ++ks) {
            unsigned ah[4], al[4];
            ldm_x4(ah[0], ah[1], ah[2], ah[3], xh_b + aoff + ks * 32);
            ldm_x4(al[0], al[1], al[2], al[3], xl_b + aoff + ks * 32);
            #pragma unroll
            for (int j = 0; j < 4; ++j) {
                unsigned h0,h1,h2,h3, e0,e1,e2,e3;
                const unsigned off = boff + (j * 16 * TSTRIDE + ks * 8) * 4;
                ldm_x4(h0,h1,h2,h3, wh_b + off);
                ldm_x4(e0,e1,e2,e3, wl_b + off);
                mma_bf16(o[2*j],   ah, h0, h1);
                mma_bf16(o[2*j+1], ah, h2, h3);
                mma_bf16(o[2*j],   ah, e0, e1);
                mma_bf16(o[2*j+1], ah, e2, e3);
                mma_bf16(o[2*j],   al, h0, h1);
                mma_bf16(o[2*j+1], al, h2, h3);
            }
        }
    }

    if (mat < 2) {
        if (mat == 0) {
            #pragma unroll
            for (int sub = 0; sub < 8; ++sub)
                #pragma unroll
                for (int i = 0; i < 4; ++i) o[sub][i] *= LOG2E;
        }
        unsigned* dh = (mat == 0) ? g_qhi : g_khi;
        unsigned* dl = (mat == 0) ? g_qlo : g_klo;
        const int ra = row0 + g0 + g;
        #pragma unroll
        for (int sub = 0; sub < 8; ++sub) {
            unsigned h, l;
            split2(o[sub][0], o[sub][1], h, l);
            dh[(size_t)ra * NPAIR + sub*4 + tig] = h;
            dl[(size_t)ra * NPAIR + sub*4 + tig] = l;
            split2(o[sub][2], o[sub][3], h, l);
            dh[(size_t)(ra+8) * NPAIR + sub*4 + tig] = h;
            dl[(size_t)(ra+8) * NPAIR + sub*4 + tig] = l;
        }
    } else {
        __syncthreads();
        float* smf = (float*)xs_hi;          // reuse: [64][68] floats
        const int rr = g0 + g;
        #pragma unroll
        for (int sub = 0; sub < 8; ++sub) {
            const int dc = sub * 8 + 2 * tig;
            smf[rr * 68 + dc]       = o[sub][0];
            smf[rr * 68 + dc + 1]   = o[sub][1];
            smf[(rr+8) * 68 + dc]   = o[sub][2];
            smf[(rr+8) * 68 + dc+1] = o[sub][3];
        }
        __syncthreads();
        const int b  = row0 / LL;
        const int lr = row0 % LL;
        const int d    = tid & 63;
        const int half = tid >> 6;
        #pragma unroll
        for (int i = 0; i < 16; ++i) {
            int kp = half * 16 + i;
            float v0 = smf[(2*kp)   * 68 + d];
            float v1 = smf[(2*kp+1) * 68 + d];
            unsigned h, l;
            split2(v0, v1, h, l);
            size_t idx = (size_t)(b * AA + d) * (LL/2) + (lr >> 1) + kp;
            g_vthi[idx] = h; g_vtlo[idx] = l;
        }
    }
}

// ---------------------------------------------------------------------------
// Kernel 2: causal flash attention.  4 warps x 32 query rows each: every
// K/V B-fragment load feeds TWO row-blocks (halves ldmatrix/smem traffic).
// Q in SMEM; K/V double-buffered cp.async; 256 regs/thread (2 CTA x 128thr).
// grid = 320 (LPT), block = 128.  smem/CTA = 110592 B.
// ---------------------------------------------------------------------------
#define TILE_U32 (64 * TSTRIDE)
#define QOFF_U32 (8 * TILE_U32)          // 18432: Q region after 2x4 KV tiles
#define QARR_U32 (128 * TSTRIDE)         // 4608 per Q array

__global__ __launch_bounds__(128, 2)
void attn_kernel(float* __restrict__ out) {
    extern __shared__ unsigned smbuf[];
    const int gx = blockIdx.x;
    const int b  = gx & 3;
    const int jj = gx >> 2;              // 0..79, longest chunks first
    int qt2, chunk;
    if (jj < 32)      { qt2 = 24 + (jj >> 2);        chunk = jj & 3; }
    else if (jj < 56) { int t = jj - 32; qt2 = 16 + t / 3;    chunk = t % 3; }
    else if (jj < 72) { int t = jj - 56; qt2 = 8 + (t >> 1);  chunk = t & 1; }
    else              { qt2 = jj - 72;               chunk = 0; }

    const int q0    = qt2 * 128;
    const int tiles = 2 * qt2 + 2;
    const int kt0   = chunk * CHT;
    const int nt    = min(CHT, tiles - kt0);

    const int tid = threadIdx.x;
    const int lane = tid & 31;
    const int g   = lane >> 2;
    const int tig = lane & 3;
    const int g0  = (tid >> 5) * 32;     // warp's 32-row strip

    const int crow = tid >> 1;           // 0..63
    const int ccol = (tid & 1) * 16;

    const unsigned smem_b = (unsigned)__cvta_generic_to_shared(smbuf);
    const unsigned boff   = bfrag_off(lane) * 4;
    const unsigned qh_b   = smem_b + QOFF_U32 * 4;
    const unsigned ql_b   = qh_b + QARR_U32 * 4;
    unsigned aoff[2];
    aoff[0] = ((g0     ) * TSTRIDE + afrag_off(lane)) * 4;
    aoff[1] = ((g0 + 16) * TSTRIDE + afrag_off(lane)) * 4;

    // ---- stage Q tile (128 rows, hi+lo) into smem via cp.async ----
    {
        const int r = tid;               // one row per thread
        const unsigned* sqh = &g_qhi[(size_t)(b*LL + q0 + r) * NPAIR];
        const unsigned* sql = &g_qlo[(size_t)(b*LL + q0 + r) * NPAIR];
        unsigned* dqh = smbuf + QOFF_U32 + r * TSTRIDE;
        unsigned* dql = smbuf + QOFF_U32 + QARR_U32 + r * TSTRIDE;
        #pragma unroll
        for (int i = 0; i < 8; ++i) {
            cpa16(dqh + 4*i, sqh + 4*i);
            cpa16(dql + 4*i, sql + 4*i);
        }
    }

    auto prefetch = [&](int bufsel, int k0) {
        unsigned* base = smbuf + bufsel * 4 * TILE_U32;
        unsigned* dkh = base              + crow * TSTRIDE + ccol;
        unsigned* dkl = base + 1*TILE_U32 + crow * TSTRIDE + ccol;
        unsigned* dvh = base + 2*TILE_U32 + crow * TSTRIDE + ccol;
        unsigned* dvl = base + 3*TILE_U32 + crow * TSTRIDE + ccol;
        const unsigned* skh = &g_khi [(size_t)(b*LL + k0 + crow) * NPAIR + ccol];
        const unsigned* skl = &g_klo [(size_t)(b*LL + k0 + crow) * NPAIR + ccol];
        const unsigned* svh = &g_vthi[(size_t)(b*AA + crow) * (LL/2) + (k0 >> 1) + ccol];
        const unsigned* svl = &g_vtlo[(size_t)(b*AA + crow) * (LL/2) + (k0 >> 1) + ccol];
        #pragma unroll
        for (int i = 0; i < 4; ++i) {
            cpa16(dkh + 4*i, skh + 4*i);
            cpa16(dkl + 4*i, skl + 4*i);
            cpa16(dvh + 4*i, svh + 4*i);
            cpa16(dvl + 4*i, svl + 4*i);
        }
        asm volatile("cp.async.commit_group;");
    };

    prefetch(0, kt0 * 64);   // group 0 = Q + first KV tile

    float o[2][8][4] = {};
    float m0[2] = {-INFINITY, -INFINITY}, m1[2] = {-INFINITY, -INFINITY};
    float l0[2] = {0.f, 0.f}, l1[2] = {0.f, 0.f};

    for (int t = 0; t < nt; ++t) {
        const int kt = kt0 + t;
        asm volatile("cp.async.wait_group 0;");
        __syncthreads();
        if (t + 1 < nt) prefetch((t + 1) & 1, (kt + 1) * 64);

        // warps fully below the diagonal skip the all-masked diag+1 tile
        const bool active = !(kt == 2*qt2 + 1 && g0 < 64);
        if (active) {
            const unsigned bufb = smem_b + ((t & 1) * 4 * TILE_U32) * 4;
            const unsigned kh_a = bufb + boff;
            const unsigned kl_a = kh_a + TILE_U32 * 4;
            const unsigned vh_a = kl_a + TILE_U32 * 4;
            const unsigned vl_a = vh_a + TILE_U32 * 4;

            float s[2][8][4];
            #pragma unroll
            for (int rb = 0; rb < 2; ++rb)
                #pragma unroll
                for (int sub = 0; sub < 8; ++sub)
                    #pragma unroll
                    for (int i = 0; i < 4; ++i) s[rb][sub][i] = 0.f;

            // ---- S = Q.K^T  (B-frags shared across both row-blocks) ----
            #pragma unroll
            for (int ks = 0; ks < 4; ++ks) {
                unsigned ah0[4], al0[4], ah1[4], al1[4];
                ldm_x4(ah0[0], ah0[1], ah0[2], ah0[3], qh_b + aoff[0] + ks * 32);
                ldm_x4(al0[0], al0[1], al0[2], al0[3], ql_b + aoff[0] + ks * 32);
                ldm_x4(ah1[0], ah1[1], ah1[2], ah1[3], qh_b + aoff[1] + ks * 32);
                ldm_x4(al1[0], al1[1], al1[2], al1[3], ql_b + aoff[1] + ks * 32);
                #pragma unroll
                for (int j = 0; j < 4; ++j) {
                    unsigned h0,h1,h2,h3, e0,e1,e2,e3;
                    const unsigned off = (j * 16 * TSTRIDE + ks * 8) * 4;
                    ldm_x4(h0,h1,h2,h3, kh_a + off);
                    ldm_x4(e0,e1,e2,e3, kl_a + off);
                    mma_bf16(s[0][2*j],   ah0, h0, h1);
                    mma_bf16(s[1][2*j],   ah1, h0, h1);
                    mma_bf16(s[0][2*j+1], ah0, h2, h3);
                    mma_bf16(s[1][2*j+1], ah1, h2, h3);
                    mma_bf16(s[0][2*j],   ah0, e0, e1);
                    mma_bf16(s[1][2*j],   ah1, e0, e1);
                    mma_bf16(s[0][2*j+1], ah0, e2, e3);
                    mma_bf16(s[1][2*j+1], ah1, e2, e3);
                    mma_bf16(s[0][2*j],   al0, h0, h1);
                    mma_bf16(s[1][2*j],   al1, h0, h1);
                    mma_bf16(s[0][2*j+1], al0, h2, h3);
                    mma_bf16(s[1][2*j+1], al1, h2, h3);
                }
            }

            if (kt >= 2*qt2) {
                const int rel = (kt - 2*qt2) * 64;
                #pragma unroll
                for (int rb = 0; rb < 2; ++rb) {
                    const int r_lo = g0 + rb * 16 + g, r_hi = r_lo + 8;
                    #pragma unroll
                    for (int sub = 0; sub < 8; ++sub) {
                        const int kc = sub * 8 + 2 * tig + rel;
                        if (kc     > r_lo) s[rb][sub][0] = -INFINITY;
                        if (kc + 1 > r_lo) s[rb][sub][1] = -INFINITY;
                        if (kc     > r_hi) s[rb][sub][2] = -INFINITY;
                        if (kc + 1 > r_hi) s[rb][sub][3] = -INFINITY;
                    }
                }
            }

            #pragma unroll
            for (int rb = 0; rb < 2; ++rb) {
                // ---- row max (quad reduce) ----
                float mt0 = -INFINITY, mt1 = -INFINITY;
                #pragma unroll
                for (int sub = 0; sub < 8; ++sub) {
                    mt0 = fmaxf(mt0, fmaxf(s[rb][sub][0], s[rb][sub][1]));
                    mt1 = fmaxf(mt1, fmaxf(s[rb][sub][2], s[rb][sub][3]));
                }
                mt0 = fmaxf(mt0, __shfl_xor_sync(0xffffffffu, mt0, 1));
                mt0 = fmaxf(mt0, __shfl_xor_sync(0xffffffffu, mt0, 2));
                mt1 = fmaxf(mt1, __shfl_xor_sync(0xffffffffu, mt1, 1));
                mt1 = fmaxf(mt1, __shfl_xor_sync(0xffffffffu, mt1, 2));

                const float mn0 = fmaxf(m0[rb], mt0);
                const float mn1 = fmaxf(m1[rb], mt1);
                const float c0f = ex2(m0[rb] - mn0);   // log2 domain
                const float c1f = ex2(m1[rb] - mn1);
                m0[rb] = mn0; m1[rb] = mn1;

                #pragma unroll
                for (int sub = 0; sub < 8; ++sub) {
                    o[rb][sub][0] *= c0f; o[rb][sub][1] *= c0f;
                    o[rb][sub][2] *= c1f; o[rb][sub][3] *= c1f;
                }

                float sum0 = 0.f, sum1 = 0.f;
                #pragma unroll
                for (int sub = 0; sub < 8; ++sub) {
                    float p0 = ex2(s[rb][sub][0] - mn0);
                    float p1 = ex2(s[rb][sub][1] - mn0);
                    float p2 = ex2(s[rb][sub][2] - mn1);
                    float p3 = ex2(s[rb][sub][3] - mn1);
                    sum0 += p0 + p1;  sum1 += p2 + p3;
                    // stash packed P back into s (reinterpret as bits)
                    unsigned h, l;
                    split2(p0, p1, h, l);
                    s[rb][sub][0] = __uint_as_float(h);
                    s[rb][sub][1] = __uint_as_float(l);
                    split2(p2, p3, h, l);
                    s[rb][sub][2] = __uint_as_float(h);
                    s[rb][sub][3] = __uint_as_float(l);
                }
                l0[rb] = l0[rb] * c0f + sum0;
                l1[rb] = l1[rb] * c1f + sum1;
            }

            // ---- O += P.V  (V B-frags shared across both row-blocks) ----
            #pragma unroll
            for (int j = 0; j < 4; ++j) {       // key chunks
                unsigned ah0[4], al0[4], ah1[4], al1[4];
                ah0[0] = __float_as_uint(s[0][2*j][0]);
                al0[0] = __float_as_uint(s[0][2*j][1]);
                ah0[1] = __float_as_uint(s[0][2*j][2]);
                al0[1] = __float_as_uint(s[0][2*j][3]);
                ah0[2] = __float_as_uint(s[0][2*j+1][0]);
                al0[2] = __float_as_uint(s[0][2*j+1][1]);
                ah0[3] = __float_as_uint(s[0][2*j+1][2]);
                al0[3] = __float_as_uint(s[0][2*j+1][3]);
                ah1[0] = __float_as_uint(s[1][2*j][0]);
                al1[0] = __float_as_uint(s[1][2*j][1]);
                ah1[1] = __float_as_uint(s[1][2*j][2]);
                al1[1] = __float_as_uint(s[1][2*j][3]);
                ah1[2] = __float_as_uint(s[1][2*j+1][0]);
                al1[2] = __float_as_uint(s[1][2*j+1][1]);
                ah1[3] = __float_as_uint(s[1][2*j+1][2]);
                al1[3] = __float_as_uint(s[1][2*j+1][3]);
                #pragma unroll
                for (int dj = 0; dj < 4; ++dj) { // dim subpairs
                    unsigned h0,h1,h2,h3, e0,e1,e2,e3;
                    const unsigned off = (dj * 16 * TSTRIDE + j * 8) * 4;
                    ldm_x4(h0,h1,h2,h3, vh_a + off);
                    ldm_x4(e0,e1,e2,e3, vl_a + off);
                    mma_bf16(o[0][2*dj],   ah0, h0, h1);
                    mma_bf16(o[1][2*dj],   ah1, h0, h1);
                    mma_bf16(o[0][2*dj+1], ah0, h2, h3);
                    mma_bf16(o[1][2*dj+1], ah1, h2, h3);
                    mma_bf16(o[0][2*dj],   ah0, e0, e1);
                    mma_bf16(o[1][2*dj],   ah1, e0, e1);
                    mma_bf16(o[0][2*dj+1], ah0, e2, e3);
                    mma_bf16(o[1][2*dj+1], ah1, e2, e3);
                    mma_bf16(o[0][2*dj],   al0, h0, h1);
                    mma_bf16(o[1][2*dj],   al1, h0, h1);
                    mma_bf16(o[0][2*dj+1], al0, h2, h3);
                    mma_bf16(o[1][2*dj+1], al1, h2, h3);
                }
            }
        }
    }

    // ---- epilogue: reduce l across the quad, then write ----
    #pragma unroll
    for (int rb = 0; rb < 2; ++rb) {
        l0[rb] += __shfl_xor_sync(0xffffffffu, l0[rb], 1);
        l0[rb] += __shfl_xor_sync(0xffffffffu, l0[rb], 2);
        l1[rb] += __shfl_xor_sync(0xffffffffu, l1[rb], 1);
        l1[rb] += __shfl_xor_sync(0xffffffffu, l1[rb], 2);
    }

    if (qt2 < 8) {
        #pragma unroll
        for (int rb = 0; rb < 2; ++rb) {
            const float inv0 = 1.f / l0[rb];
            const float inv1 = 1.f / l1[rb];
            float* base0 = out + ((size_t)(b * LL + q0 + g0 + rb*16 + g)) * AA;
            float* base1 = base0 + (size_t)8 * AA;
            #pragma unroll
            for (int sub = 0; sub < 8; ++sub) {
                const int dcol = sub * 8 + 2 * tig;
                *(float2*)&base0[dcol] = make_float2(o[rb][sub][0] * inv0, o[rb][sub][1] * inv0);
                *(float2*)&base1[dcol] = make_float2(o[rb][sub][2] * inv1, o[rb][sub][3] * inv1);
            }
        }
    } else {
        const int slot = (b * NQT + qt2) * NCH + chunk;
        float* po = g_pO + (size_t)slot * 8192;
        #pragma unroll
        for (int rb = 0; rb < 2; ++rb) {
            const int r0w = g0 + rb*16 + g;
            #pragma unroll
            for (int sub = 0; sub < 8; ++sub) {
                const int dcol = sub * 8 + 2 * tig;
                *(float2*)&po[r0w * 64 + dcol]       = make_float2(o[rb][sub][0], o[rb][sub][1]);
                *(float2*)&po[(r0w + 8) * 64 + dcol] = make_float2(o[rb][sub][2], o[rb][sub][3]);
            }
            if (tig == 0) {
                g_pm[slot * 128 + r0w]     = m0[rb];
                g_pm[slot * 128 + r0w + 8] = m1[rb];
                g_pl[slot * 128 + r0w]     = l0[rb];
                g_pl[slot * 128 + r0w + 8] = l1[rb];
            }
        }
    }
}

// ---------------------------------------------------------------------------
// Kernel 3: merge split-KV partials (multi-chunk jobs only: qt2 >= 8).
// grid = 384 (96 bq x 4 quarters), block = 256.
// ---------------------------------------------------------------------------
__global__ __launch_bounds__(256)
void merge_kernel(float* __restrict__ out) {
    const int bqi     = blockIdx.x >> 2;         // 0..95
    const int quarter = blockIdx.x & 3;
    const int b   = bqi / 24;
    const int qt2 = 8 + bqi % 24;
    const int bq  = b * 32 + qt2;
    const int nch = (2 * qt2 + 17) >> 4;
    const int base_slot = bq * NCH;

    for (int e = threadIdx.x; e < 2048; e += 256) {
        const int row = quarter * 32 + (e >> 6);
        const int col = e & 63;
        float M = -INFINITY;
        #pragma unroll
        for (int c = 0; c < NCH; ++c)
            if (c < nch) M = fmaxf(M, g_pm[(base_slot + c) * 128 + row]);
        float denom = 0.f, acc = 0.f;
        #pragma unroll
        for (int c = 0; c < NCH; ++c) {
            if (c < nch) {
                float w = ex2(g_pm[(base_slot + c) * 128 + row] - M);
                denom += w * g_pl[(base_slot + c) * 128 + row];
                acc   += w * g_pO[(size_t)(base_slot + c) * 8192 + row * 64 + col];
            }
        }
        out[((size_t)(b * LL + qt2 * 128 + row)) * 64 + col] = acc / denom;
    }
}

// ---------------------------------------------------------------------------
extern "C" void kernel_launch(void* const* d_in, const int* in_sizes, int n_in,
                              void* d_out, int out_size) {
    (void)in_sizes; (void)n_in; (void)out_size;
    const float* x  = (const float*)d_in[0];
    const float* Wq = (const float*)d_in[1];
    const float* Wk = (const float*)d_in[2];
    const float* Wv = (const float*)d_in[3];
    float* out = (float*)d_out;

    prepw_kernel<<<32, 256>>>(Wq, Wk, Wv);
    {
        dim3 grid(3, NROWS / 64);
        qkv_kernel<<<grid, 128>>>(x);
    }
    {
        size_t smem = (size_t)(8 * TILE_U32 + 2 * QARR_U32) * sizeof(unsigned); // 110592 B
        cudaFuncSetAttribute(attn_kernel, cudaFuncAttributeMaxDynamicSharedMemorySize, (int)smem);
        attn_kernel<<<320, 128, smem>>>(out);
    }
    merge_kernel<<<384, 256>>>(out);
}

// round 14
// speedup vs baseline: 1.0852x; 1.0852x over previous
#include <cuda_runtime.h>
#include <cuda_bf16.h>
#include <cuda_fp16.h>
#include <math.h>

#define BB 4
#define LL 4096
#define DD 256
#define AA 64
#define NROWS (BB*LL)
#define NPAIR 32           // 64 elems -> 32 f16x2 pairs
#define DPAIR 128          // 256 dims -> 128 pairs
#define TSTRIDE 36         // smem tile row stride (u32): 144B rows, ldmatrix conflict-free
#define NCH 4              // max chunks per 128-row query tile
#define CHT 16             // key-tiles per chunk
#define NQT 32             // 128-row query tiles per batch
#define LOG2E 1.4426950408889634f

// Packed fp16 hi/lo splits
__device__ unsigned g_qhi[NROWS*NPAIR], g_qlo[NROWS*NPAIR];
__device__ unsigned g_khi[NROWS*NPAIR], g_klo[NROWS*NPAIR];
__device__ unsigned g_vthi[BB*AA*(LL/2)], g_vtlo[BB*AA*(LL/2)];  // [b][d][keypair]
__device__ unsigned g_wtp_hi[3*AA*DPAIR], g_wtp_lo[3*AA*DPAIR];  // [mat][a][dpair]
// Split-KV partials: slot = (b*NQT+qt2)*NCH+chunk, 128 rows x 64 cols
__device__ float g_pO[BB*NQT*NCH*128*64];
__device__ float g_pm[BB*NQT*NCH*128];   // log2 domain
__device__ float g_pl[BB*NQT*NCH*128];

// ---------------------------------------------------------------------------
// fp16 hi/lo split of a float pair (residual f - (float)fp16(f) is exact fp32)
// dropped product term ~2^-22 relative -> scores effectively exact.
// ---------------------------------------------------------------------------
__device__ __forceinline__ void split2h(float f0, float f1, unsigned &hi, unsigned &lo) {
    __half2 h = __floats2half2_rn(f0, f1);
    float r0 = f0 - __half2float(__low2half(h));
    float r1 = f1 - __half2float(__high2half(h));
    __half2 l2 = __floats2half2_rn(r0, r1);
    hi = *(unsigned*)&h;
    lo = *(unsigned*)&l2;
}

__device__ __forceinline__ unsigned pack2h(float f0, float f1) {
    __half2 h = __floats2half2_rn(f0, f1);
    return *(unsigned*)&h;
}

__device__ __forceinline__ float ex2(float x) {
    float y;
    asm("ex2.approx.ftz.f32 %0, %1;" : "=f"(y) : "f"(x));
    return y;
}

__device__ __forceinline__ void mma_f16(float (&d)[4], const unsigned (&a)[4],
                                        unsigned b0, unsigned b1) {
    asm volatile(
        "mma.sync.aligned.m16n8k16.row.col.f32.f16.f16.f32 "
        "{%0,%1,%2,%3}, {%4,%5,%6,%7}, {%8,%9}, {%0,%1,%2,%3};"
        : "+f"(d[0]), "+f"(d[1]), "+f"(d[2]), "+f"(d[3])
        : "r"(a[0]), "r"(a[1]), "r"(a[2]), "r"(a[3]), "r"(b0), "r"(b1));
}

__device__ __forceinline__ void ldm_x4(unsigned &r0, unsigned &r1,
                                       unsigned &r2, unsigned &r3, unsigned addr) {
    asm volatile("ldmatrix.sync.aligned.m8n8.x4.shared.b16 {%0,%1,%2,%3}, [%4];"
                 : "=r"(r0), "=r"(r1), "=r"(r2), "=r"(r3) : "r"(addr));
}

__device__ __forceinline__ void cpa16(void* s, const void* g) {
    unsigned sa = (unsigned)__cvta_generic_to_shared(s);
    asm volatile("cp.async.cg.shared.global [%0], [%1], 16;" :: "r"(sa), "l"(g));
}

// B-fragment lane offset (u32 units)
__device__ __forceinline__ unsigned bfrag_off(int lane) {
    return ((lane >> 4) * 8 * TSTRIDE + (lane & 7) * TSTRIDE + ((lane >> 3) & 1) * 4);
}
// A-fragment lane offset (u32 units)
__device__ __forceinline__ unsigned afrag_off(int lane) {
    return (((lane & 7) + ((lane >> 3) & 1) * 8) * TSTRIDE + (lane >> 4) * 4);
}

// ---------------------------------------------------------------------------
// Kernel 0: split W into packed [mat][a][dpair] hi/lo (tiny).
// ---------------------------------------------------------------------------
__global__ void prepw_kernel(const float* __restrict__ Wq,
                             const float* __restrict__ Wk,
                             const float* __restrict__ Wv) {
    const int total = 3 * AA * DPAIR;
    for (int i = blockIdx.x * blockDim.x + threadIdx.x; i < total;
         i += gridDim.x * blockDim.x) {
        int m = i / (AA * DPAIR);
        int r = i % (AA * DPAIR);
        int a = r >> 7, p = r & 127;
        const float* W = (m == 0) ? Wq : (m == 1) ? Wk : Wv;
        float w0 = W[(size_t)(2*p)   * AA + a];
        float w1 = W[(size_t)(2*p+1) * AA + a];
        split2h(w0, w1, g_wtp_hi[i], g_wtp_lo[i]);
    }
}

// ---------------------------------------------------------------------------
// Kernel 1: QKV projection on tensor cores (fp16 3-term split).
// grid = (3, NROWS/64), block = 128.
// ---------------------------------------------------------------------------
__global__ __launch_bounds__(128)
void qkv_kernel(const float* __restrict__ x) {
    __shared__ unsigned xs_hi[64*TSTRIDE], xs_lo[64*TSTRIDE];
    __shared__ unsigned ws_hi[64*TSTRIDE], ws_lo[64*TSTRIDE];

    const int mat  = blockIdx.x;
    const int row0 = blockIdx.y * 64;
    const int tid  = threadIdx.x;
    const int wid  = tid >> 5;
    const int lane = tid & 31;
    const int g    = lane >> 2;
    const int tig  = lane & 3;
    const int g0   = wid * 16;

    const unsigned xh_b = (unsigned)__cvta_generic_to_shared(xs_hi);
    const unsigned xl_b = (unsigned)__cvta_generic_to_shared(xs_lo);
    const unsigned wh_b = (unsigned)__cvta_generic_to_shared(ws_hi);
    const unsigned wl_b = (unsigned)__cvta_generic_to_shared(ws_lo);
    const unsigned aoff = (g0 * TSTRIDE + afrag_off(lane)) * 4;
    const unsigned boff = bfrag_off(lane) * 4;

    float o[8][4] = {};

    for (int d0 = 0; d0 < DD; d0 += 64) {
        __syncthreads();
        {
            const int r = tid >> 1;
            const int p0 = (tid & 1) * 16;
            const float* src = x + (size_t)(row0 + r) * DD + d0 + p0 * 2;
            unsigned* dh = &xs_hi[r * TSTRIDE + p0];
            unsigned* dl = &xs_lo[r * TSTRIDE + p0];
            #pragma unroll
            for (int i = 0; i < 8; ++i) {
                float4 f = *(const float4*)(src + 4*i);
                split2h(f.x, f.y, dh[2*i],   dl[2*i]);
                split2h(f.z, f.w, dh[2*i+1], dl[2*i+1]);
            }
        }
        {
            const int a  = tid >> 1;
            const int p0 = (tid & 1) * 16;
            const uint4* sh = (const uint4*)&g_wtp_hi[(size_t)mat*AA*DPAIR + a*DPAIR + (d0>>1) + p0];
            const uint4* sl = (const uint4*)&g_wtp_lo[(size_t)mat*AA*DPAIR + a*DPAIR + (d0>>1) + p0];
            uint4* dh = (uint4*)&ws_hi[a * TSTRIDE + p0];
            uint4* dl = (uint4*)&ws_lo[a * TSTRIDE + p0];
            #pragma unroll
            for (int i = 0; i < 4; ++i) { dh[i] = sh[i]; dl[i] = sl[i]; }
        }
        __syncthreads();

        #pragma unroll
        for (int ks = 0; ks < 4; ++ks) {
            unsigned ah[4], al[4];
            ldm_x4(ah[0], ah[1], ah[2], ah[3], xh_b + aoff + ks * 32);
            ldm_x4(al[0], al[1], al[2], al[3], xl_b + aoff + ks * 32);
            #pragma unroll
            for (int j = 0; j < 4; ++j) {
                unsigned h0,h1,h2,h3, e0,e1,e2,e3;
                const unsigned off = boff + (j * 16 * TSTRIDE + ks * 8) * 4;
                ldm_x4(h0,h1,h2,h3, wh_b + off);
                ldm_x4(e0,e1,e2,e3, wl_b + off);
                mma_f16(o[2*j],   ah, h0, h1);
                mma_f16(o[2*j+1], ah, h2, h3);
                mma_f16(o[2*j],   ah, e0, e1);
                mma_f16(o[2*j+1], ah, e2, e3);
                mma_f16(o[2*j],   al, h0, h1);
                mma_f16(o[2*j+1], al, h2, h3);
            }
        }
    }

    if (mat < 2) {
        if (mat == 0) {
            #pragma unroll
            for (int sub = 0; sub < 8; ++sub)
                #pragma unroll
                for (int i = 0; i < 4; ++i) o[sub][i] *= LOG2E;
        }
        unsigned* dh = (mat == 0) ? g_qhi : g_khi;
        unsigned* dl = (mat == 0) ? g_qlo : g_klo;
        const int ra = row0 + g0 + g;
        #pragma unroll
        for (int sub = 0; sub < 8; ++sub) {
            unsigned h, l;
            split2h(o[sub][0], o[sub][1], h, l);
            dh[(size_t)ra * NPAIR + sub*4 + tig] = h;
            dl[(size_t)ra * NPAIR + sub*4 + tig] = l;
            split2h(o[sub][2], o[sub][3], h, l);
            dh[(size_t)(ra+8) * NPAIR + sub*4 + tig] = h;
            dl[(size_t)(ra+8) * NPAIR + sub*4 + tig] = l;
        }
    } else {
        __syncthreads();
        float* smf = (float*)xs_hi;          // reuse: [64][68] floats
        const int rr = g0 + g;
        #pragma unroll
        for (int sub = 0; sub < 8; ++sub) {
            const int dc = sub * 8 + 2 * tig;
            smf[rr * 68 + dc]       = o[sub][0];
            smf[rr * 68 + dc + 1]   = o[sub][1];
            smf[(rr+8) * 68 + dc]   = o[sub][2];
            smf[(rr+8) * 68 + dc+1] = o[sub][3];
        }
        __syncthreads();
        const int b  = row0 / LL;
        const int lr = row0 % LL;
        const int d    = tid & 63;
        const int half = tid >> 6;
        #pragma unroll
        for (int i = 0; i < 16; ++i) {
            int kp = half * 16 + i;
            float v0 = smf[(2*kp)   * 68 + d];
            float v1 = smf[(2*kp+1) * 68 + d];
            unsigned h, l;
            split2h(v0, v1, h, l);
            size_t idx = (size_t)(b * AA + d) * (LL/2) + (lr >> 1) + kp;
            g_vthi[idx] = h; g_vtlo[idx] = l;
        }
    }
}

// ---------------------------------------------------------------------------
// Kernel 2: causal flash attention (fp16).  Q in SMEM; K/V double-buffered
// cp.async; QK = 3-product fp16 split; P single fp16 -> PV = 2 products.
// grid = 320 (LPT), block = 256.  smem/CTA = 110592 B.
// ---------------------------------------------------------------------------
#define TILE_U32 (64 * TSTRIDE)
#define QOFF_U32 (8 * TILE_U32)          // 18432: Q region after 2x4 KV tiles
#define QARR_U32 (128 * TSTRIDE)         // 4608 per Q array

__global__ __launch_bounds__(256, 2)
void attn_kernel(float* __restrict__ out) {
    extern __shared__ unsigned smbuf[];
    const int gx = blockIdx.x;
    const int b  = gx & 3;
    const int jj = gx >> 2;              // 0..79, longest chunks first
    int qt2, chunk;
    if (jj < 32)      { qt2 = 24 + (jj >> 2);        chunk = jj & 3; }
    else if (jj < 56) { int t = jj - 32; qt2 = 16 + t / 3;    chunk = t % 3; }
    else if (jj < 72) { int t = jj - 56; qt2 = 8 + (t >> 1);  chunk = t & 1; }
    else              { qt2 = jj - 72;               chunk = 0; }

    const int q0    = qt2 * 128;
    const int tiles = 2 * qt2 + 2;
    const int kt0   = chunk * CHT;
    const int nt    = min(CHT, tiles - kt0);

    const int tid = threadIdx.x;
    const int lane = tid & 31;
    const int g   = lane >> 2;
    const int tig = lane & 3;
    const int g0  = (tid >> 5) * 16;

    const int crow = tid >> 2;
    const int ccol = (tid & 3) * 8;

    const unsigned smem_b = (unsigned)__cvta_generic_to_shared(smbuf);
    const unsigned boff   = bfrag_off(lane) * 4;
    const unsigned qh_b   = smem_b + QOFF_U32 * 4;
    const unsigned ql_b   = qh_b + QARR_U32 * 4;
    const unsigned aoff   = (g0 * TSTRIDE + afrag_off(lane)) * 4;

    // ---- stage Q tile (128 rows, hi+lo) into smem via cp.async ----
    {
        const int r   = tid >> 1;          // 0..127
        const int c0q = (tid & 1) * 16;
        const unsigned* sqh = &g_qhi[(size_t)(b*LL + q0 + r) * NPAIR + c0q];
        const unsigned* sql = &g_qlo[(size_t)(b*LL + q0 + r) * NPAIR + c0q];
        unsigned* dqh = smbuf + QOFF_U32 + r * TSTRIDE + c0q;
        unsigned* dql = smbuf + QOFF_U32 + QARR_U32 + r * TSTRIDE + c0q;
        #pragma unroll
        for (int i = 0; i < 4; ++i) {
            cpa16(dqh + 4*i, sqh + 4*i);
            cpa16(dql + 4*i, sql + 4*i);
        }
    }

    auto prefetch = [&](int bufsel, int k0) {
        unsigned* base = smbuf + bufsel * 4 * TILE_U32;
        unsigned* dkh = base              + crow * TSTRIDE + ccol;
        unsigned* dkl = base + 1*TILE_U32 + crow * TSTRIDE + ccol;
        unsigned* dvh = base + 2*TILE_U32 + crow * TSTRIDE + ccol;
        unsigned* dvl = base + 3*TILE_U32 + crow * TSTRIDE + ccol;
        const unsigned* skh = &g_khi [(size_t)(b*LL + k0 + crow) * NPAIR + ccol];
        const unsigned* skl = &g_klo [(size_t)(b*LL + k0 + crow) * NPAIR + ccol];
        const unsigned* svh = &g_vthi[(size_t)(b*AA + crow) * (LL/2) + (k0 >> 1) + ccol];
        const unsigned* svl = &g_vtlo[(size_t)(b*AA + crow) * (LL/2) + (k0 >> 1) + ccol];
        cpa16(dkh, skh); cpa16(dkh + 4, skh + 4);
        cpa16(dkl, skl); cpa16(dkl + 4, skl + 4);
        cpa16(dvh, svh); cpa16(dvh + 4, svh + 4);
        cpa16(dvl, svl); cpa16(dvl + 4, svl + 4);
        asm volatile("cp.async.commit_group;");
    };

    prefetch(0, kt0 * 64);   // group 0 = Q + first KV tile

    float o[8][4] = {};
    float m0 = -INFINITY, m1 = -INFINITY, l0 = 0.f, l1 = 0.f;

    for (int t = 0; t < nt; ++t) {
        const int kt = kt0 + t;
        asm volatile("cp.async.wait_group 0;");
        __syncthreads();
        if (t + 1 < nt) prefetch((t + 1) & 1, (kt + 1) * 64);

        const bool active = !(kt == 2*qt2 + 1 && g0 < 64);
        if (active) {
            const unsigned bufb = smem_b + ((t & 1) * 4 * TILE_U32) * 4;
            const unsigned kh_a = bufb + boff;
            const unsigned kl_a = kh_a + TILE_U32 * 4;
            const unsigned vh_a = kl_a + TILE_U32 * 4;
            const unsigned vl_a = vh_a + TILE_U32 * 4;

            float s[8][4];
            #pragma unroll
            for (int sub = 0; sub < 8; ++sub)
                #pragma unroll
                for (int i = 0; i < 4; ++i) s[sub][i] = 0.f;

            // ---- S = Q.K^T  (3-product fp16 split) ----
            #pragma unroll
            for (int ks = 0; ks < 4; ++ks) {
                unsigned ah[4], al[4];
                ldm_x4(ah[0], ah[1], ah[2], ah[3], qh_b + aoff + ks * 32);
                ldm_x4(al[0], al[1], al[2], al[3], ql_b + aoff + ks * 32);
                #pragma unroll
                for (int j = 0; j < 4; ++j) {
                    unsigned h0,h1,h2,h3, e0,e1,e2,e3;
                    const unsigned off = (j * 16 * TSTRIDE + ks * 8) * 4;
                    ldm_x4(h0,h1,h2,h3, kh_a + off);
                    ldm_x4(e0,e1,e2,e3, kl_a + off);
                    mma_f16(s[2*j],   ah, h0, h1);
                    mma_f16(s[2*j+1], ah, h2, h3);
                    mma_f16(s[2*j],   ah, e0, e1);
                    mma_f16(s[2*j+1], ah, e2, e3);
                    mma_f16(s[2*j],   al, h0, h1);
                    mma_f16(s[2*j+1], al, h2, h3);
                }
            }

            if (kt >= 2*qt2) {
                const int rel = (kt - 2*qt2) * 64;
                #pragma unroll
                for (int sub = 0; sub < 8; ++sub) {
                    const int kc = sub * 8 + 2 * tig + rel;
                    const int r_lo = g0 + g, r_hi = r_lo + 8;
                    if (kc     > r_lo) s[sub][0] = -INFINITY;
                    if (kc + 1 > r_lo) s[sub][1] = -INFINITY;
                    if (kc     > r_hi) s[sub][2] = -INFINITY;
                    if (kc + 1 > r_hi) s[sub][3] = -INFINITY;
                }
            }

            // ---- row max (quad reduce) ----
            float mt0 = -INFINITY, mt1 = -INFINITY;
            #pragma unroll
            for (int sub = 0; sub < 8; ++sub) {
                mt0 = fmaxf(mt0, fmaxf(s[sub][0], s[sub][1]));
                mt1 = fmaxf(mt1, fmaxf(s[sub][2], s[sub][3]));
            }
            mt0 = fmaxf(mt0, __shfl_xor_sync(0xffffffffu, mt0, 1));
            mt0 = fmaxf(mt0, __shfl_xor_sync(0xffffffffu, mt0, 2));
            mt1 = fmaxf(mt1, __shfl_xor_sync(0xffffffffu, mt1, 1));
            mt1 = fmaxf(mt1, __shfl_xor_sync(0xffffffffu, mt1, 2));

            const float mn0 = fmaxf(m0, mt0);
            const float mn1 = fmaxf(m1, mt1);
            const float c0f = ex2(m0 - mn0);   // log2 domain
            const float c1f = ex2(m1 - mn1);
            m0 = mn0; m1 = mn1;

            // rescale O once
            #pragma unroll
            for (int sub = 0; sub < 8; ++sub) {
                o[sub][0] *= c0f; o[sub][1] *= c0f;
                o[sub][2] *= c1f; o[sub][3] *= c1f;
            }

            // ---- exp + single-fp16 pack of P ----
            unsigned ph[8][2];
            float sum0 = 0.f, sum1 = 0.f;
            #pragma unroll
            for (int sub = 0; sub < 8; ++sub) {
                float p0 = ex2(s[sub][0] - mn0);
                float p1 = ex2(s[sub][1] - mn0);
                float p2 = ex2(s[sub][2] - mn1);
                float p3 = ex2(s[sub][3] - mn1);
                sum0 += p0 + p1;  sum1 += p2 + p3;
                ph[sub][0] = pack2h(p0, p1);
                ph[sub][1] = pack2h(p2, p3);
            }
            l0 = l0 * c0f + sum0;   // per-lane partials; quad-reduced at epilogue
            l1 = l1 * c1f + sum1;

            // ---- O += P.V  (2 products: P.Vh + P.Vl) ----
            #pragma unroll
            for (int j = 0; j < 4; ++j) {       // key chunks
                unsigned a_[4] = {ph[2*j][0], ph[2*j][1], ph[2*j+1][0], ph[2*j+1][1]};
                #pragma unroll
                for (int dj = 0; dj < 4; ++dj) { // dim subpairs
                    unsigned h0,h1,h2,h3, e0,e1,e2,e3;
                    const unsigned off = (dj * 16 * TSTRIDE + j * 8) * 4;
                    ldm_x4(h0,h1,h2,h3, vh_a + off);
                    ldm_x4(e0,e1,e2,e3, vl_a + off);
                    mma_f16(o[2*dj],   a_, h0, h1);
                    mma_f16(o[2*dj+1], a_, h2, h3);
                    mma_f16(o[2*dj],   a_, e0, e1);
                    mma_f16(o[2*dj+1], a_, e2, e3);
                }
            }
        }
    }

    // ---- epilogue: reduce l across the quad, then write ----
    l0 += __shfl_xor_sync(0xffffffffu, l0, 1);
    l0 += __shfl_xor_sync(0xffffffffu, l0, 2);
    l1 += __shfl_xor_sync(0xffffffffu, l1, 1);
    l1 += __shfl_xor_sync(0xffffffffu, l1, 2);

    if (qt2 < 8) {
        const float inv0 = 1.f / l0;
        const float inv1 = 1.f / l1;
        float* base0 = out + ((size_t)(b * LL + q0 + g0 + g)) * AA;
        float* base1 = base0 + (size_t)8 * AA;
        #pragma unroll
        for (int sub = 0; sub < 8; ++sub) {
            const int dcol = sub * 8 + 2 * tig;
            *(float2*)&base0[dcol] = make_float2(o[sub][0] * inv0, o[sub][1] * inv0);
            *(float2*)&base1[dcol] = make_float2(o[sub][2] * inv1, o[sub][3] * inv1);
        }
    } else {
        const int slot = (b * NQT + qt2) * NCH + chunk;
        float* po = g_pO + (size_t)slot * 8192;
        #pragma unroll
        for (int sub = 0; sub < 8; ++sub) {
            const int dcol = sub * 8 + 2 * tig;
            *(float2*)&po[(g0 + g) * 64 + dcol]     = make_float2(o[sub][0], o[sub][1]);
            *(float2*)&po[(g0 + g + 8) * 64 + dcol] = make_float2(o[sub][2], o[sub][3]);
        }
        if (tig == 0) {
            g_pm[slot * 128 + g0 + g]     = m0;
            g_pm[slot * 128 + g0 + g + 8] = m1;
            g_pl[slot * 128 + g0 + g]     = l0;
            g_pl[slot * 128 + g0 + g + 8] = l1;
        }
    }
}

// ---------------------------------------------------------------------------
// Kernel 3: merge split-KV partials (qt2 >= 8).  grid = 384, block = 256.
// ---------------------------------------------------------------------------
__global__ __launch_bounds__(256)
void merge_kernel(float* __restrict__ out) {
    const int bqi     = blockIdx.x >> 2;
    const int quarter = blockIdx.x & 3;
    const int b   = bqi / 24;
    const int qt2 = 8 + bqi % 24;
    const int bq  = b * 32 + qt2;
    const int nch = (2 * qt2 + 17) >> 4;
    const int base_slot = bq * NCH;

    for (int e = threadIdx.x; e < 2048; e += 256) {
        const int row = quarter * 32 + (e >> 6);
        const int col = e & 63;
        float M = -INFINITY;
        #pragma unroll
        for (int c = 0; c < NCH; ++c)
            if (c < nch) M = fmaxf(M, g_pm[(base_slot + c) * 128 + row]);
        float denom = 0.f, acc = 0.f;
        #pragma unroll
        for (int c = 0; c < NCH; ++c) {
            if (c < nch) {
                float w = ex2(g_pm[(base_slot + c) * 128 + row] - M);
                denom += w * g_pl[(base_slot + c) * 128 + row];
                acc   += w * g_pO[(size_t)(base_slot + c) * 8192 + row * 64 + col];
            }
        }
        out[((size_t)(b * LL + qt2 * 128 + row)) * 64 + col] = acc / denom;
    }
}

// ---------------------------------------------------------------------------
extern "C" void kernel_launch(void* const* d_in, const int* in_sizes, int n_in,
                              void* d_out, int out_size) {
    (void)in_sizes; (void)n_in; (void)out_size;
    const float* x  = (const float*)d_in[0];
    const float* Wq = (const float*)d_in[1];
    const float* Wk = (const float*)d_in[2];
    const float* Wv = (const float*)d_in[3];
    float* out = (float*)d_out;

    prepw_kernel<<<32, 256>>>(Wq, Wk, Wv);
    {
        dim3 grid(3, NROWS / 64);
        qkv_kernel<<<grid, 128>>>(x);
    }
    {
        size_t smem = (size_t)(8 * TILE_U32 + 2 * QARR_U32) * sizeof(unsigned); // 110592 B
        cudaFuncSetAttribute(attn_kernel, cudaFuncAttributeMaxDynamicSharedMemorySize, (int)smem);
        attn_kernel<<<320, 256, smem>>>(out);
    }
    merge_kernel<<<384, 256>>>(out);
}

// round 16
// speedup vs baseline: 1.2841x; 1.1833x over previous
#include <cuda_runtime.h>
#include <cuda_bf16.h>
#include <cuda_fp16.h>
#include <math.h>

#define BB 4
#define LL 4096
#define DD 256
#define AA 64
#define NROWS (BB*LL)
#define NPAIR 32           // 64 elems -> 32 f16x2 pairs
#define DPAIR 128          // 256 dims -> 128 pairs
#define TSTRIDE 36         // smem tile row stride (u32): 144B rows, ldmatrix conflict-free
#define NCH 4              // max chunks per 128-row query tile
#define CHT 16             // key-tiles per chunk
#define NQT 32             // 128-row query tiles per batch
#define LOG2E 1.4426950408889634f

// Packed fp16 hi/lo splits (V is single fp16)
__device__ unsigned g_qhi[NROWS*NPAIR], g_qlo[NROWS*NPAIR];
__device__ unsigned g_khi[NROWS*NPAIR], g_klo[NROWS*NPAIR];
__device__ unsigned g_vthi[BB*AA*(LL/2)];                        // [b][d][keypair]
__device__ unsigned g_wtp_hi[3*AA*DPAIR], g_wtp_lo[3*AA*DPAIR];  // [mat][a][dpair]
// Split-KV partials: slot = (b*NQT+qt2)*NCH+chunk, 128 rows x 64 cols
__device__ float g_pO[BB*NQT*NCH*128*64];
__device__ float g_pm[BB*NQT*NCH*128];   // log2 domain
__device__ float g_pl[BB*NQT*NCH*128];

// ---------------------------------------------------------------------------
__device__ __forceinline__ void split2h(float f0, float f1, unsigned &hi, unsigned &lo) {
    __half2 h = __floats2half2_rn(f0, f1);
    float r0 = f0 - __half2float(__low2half(h));
    float r1 = f1 - __half2float(__high2half(h));
    __half2 l2 = __floats2half2_rn(r0, r1);
    hi = *(unsigned*)&h;
    lo = *(unsigned*)&l2;
}

__device__ __forceinline__ unsigned pack2h(float f0, float f1) {
    __half2 h = __floats2half2_rn(f0, f1);
    return *(unsigned*)&h;
}

__device__ __forceinline__ float ex2(float x) {
    float y;
    asm("ex2.approx.ftz.f32 %0, %1;" : "=f"(y) : "f"(x));
    return y;
}

__device__ __forceinline__ void mma_f16(float (&d)[4], const unsigned (&a)[4],
                                        unsigned b0, unsigned b1) {
    asm volatile(
        "mma.sync.aligned.m16n8k16.row.col.f32.f16.f16.f32 "
        "{%0,%1,%2,%3}, {%4,%5,%6,%7}, {%8,%9}, {%0,%1,%2,%3};"
        : "+f"(d[0]), "+f"(d[1]), "+f"(d[2]), "+f"(d[3])
        : "r"(a[0]), "r"(a[1]), "r"(a[2]), "r"(a[3]), "r"(b0), "r"(b1));
}

__device__ __forceinline__ void ldm_x4(unsigned &r0, unsigned &r1,
                                       unsigned &r2, unsigned &r3, unsigned addr) {
    asm volatile("ldmatrix.sync.aligned.m8n8.x4.shared.b16 {%0,%1,%2,%3}, [%4];"
                 : "=r"(r0), "=r"(r1), "=r"(r2), "=r"(r3) : "r"(addr));
}

__device__ __forceinline__ void cpa16(void* s, const void* g) {
    unsigned sa = (unsigned)__cvta_generic_to_shared(s);
    asm volatile("cp.async.cg.shared.global [%0], [%1], 16;" :: "r"(sa), "l"(g));
}

// B-fragment lane offset (u32 units)
__device__ __forceinline__ unsigned bfrag_off(int lane) {
    return ((lane >> 4) * 8 * TSTRIDE + (lane & 7) * TSTRIDE + ((lane >> 3) & 1) * 4);
}
// A-fragment lane offset (u32 units)
__device__ __forceinline__ unsigned afrag_off(int lane) {
    return (((lane & 7) + ((lane >> 3) & 1) * 8) * TSTRIDE + (lane >> 4) * 4);
}

// ---------------------------------------------------------------------------
// Kernel 0: split W into packed [mat][a][dpair] hi/lo (tiny).
// ---------------------------------------------------------------------------
__global__ void prepw_kernel(const float* __restrict__ Wq,
                             const float* __restrict__ Wk,
                             const float* __restrict__ Wv) {
    const int total = 3 * AA * DPAIR;
    for (int i = blockIdx.x * blockDim.x + threadIdx.x; i < total;
         i += gridDim.x * blockDim.x) {
        int m = i / (AA * DPAIR);
        int r = i % (AA * DPAIR);
        int a = r >> 7, p = r & 127;
        const float* W = (m == 0) ? Wq : (m == 1) ? Wk : Wv;
        float w0 = W[(size_t)(2*p)   * AA + a];
        float w1 = W[(size_t)(2*p+1) * AA + a];
        split2h(w0, w1, g_wtp_hi[i], g_wtp_lo[i]);
    }
}

// ---------------------------------------------------------------------------
// Kernel 1: QKV projection on tensor cores (fp16 3-term split).
// grid = (3, NROWS/64), block = 128.
// ---------------------------------------------------------------------------
__global__ __launch_bounds__(128)
void qkv_kernel(const float* __restrict__ x) {
    __shared__ unsigned xs_hi[64*TSTRIDE], xs_lo[64*TSTRIDE];
    __shared__ unsigned ws_hi[64*TSTRIDE], ws_lo[64*TSTRIDE];

    const int mat  = blockIdx.x;
    const int row0 = blockIdx.y * 64;
    const int tid  = threadIdx.x;
    const int wid  = tid >> 5;
    const int lane = tid & 31;
    const int g    = lane >> 2;
    const int tig  = lane & 3;
    const int g0   = wid * 16;

    const unsigned xh_b = (unsigned)__cvta_generic_to_shared(xs_hi);
    const unsigned xl_b = (unsigned)__cvta_generic_to_shared(xs_lo);
    const unsigned wh_b = (unsigned)__cvta_generic_to_shared(ws_hi);
    const unsigned wl_b = (unsigned)__cvta_generic_to_shared(ws_lo);
    const unsigned aoff = (g0 * TSTRIDE + afrag_off(lane)) * 4;
    const unsigned boff = bfrag_off(lane) * 4;

    float o[8][4] = {};

    for (int d0 = 0; d0 < DD; d0 += 64) {
        __syncthreads();
        {
            const int r = tid >> 1;
            const int p0 = (tid & 1) * 16;
            const float* src = x + (size_t)(row0 + r) * DD + d0 + p0 * 2;
            unsigned* dh = &xs_hi[r * TSTRIDE + p0];
            unsigned* dl = &xs_lo[r * TSTRIDE + p0];
            #pragma unroll
            for (int i = 0; i < 8; ++i) {
                float4 f = *(const float4*)(src + 4*i);
                split2h(f.x, f.y, dh[2*i],   dl[2*i]);
                split2h(f.z, f.w, dh[2*i+1], dl[2*i+1]);
            }
        }
        {
            const int a  = tid >> 1;
            const int p0 = (tid & 1) * 16;
            const uint4* sh = (const uint4*)&g_wtp_hi[(size_t)mat*AA*DPAIR + a*DPAIR + (d0>>1) + p0];
            const uint4* sl = (const uint4*)&g_wtp_lo[(size_t)mat*AA*DPAIR + a*DPAIR + (d0>>1) + p0];
            uint4* dh = (uint4*)&ws_hi[a * TSTRIDE + p0];
            uint4* dl = (uint4*)&ws_lo[a * TSTRIDE + p0];
            #pragma unroll
            for (int i = 0; i < 4; ++i) { dh[i] = sh[i]; dl[i] = sl[i]; }
        }
        __syncthreads();

        #pragma unroll
        for (int ks = 0; ks < 4; ++ks) {
            unsigned ah[4], al[4];
            ldm_x4(ah[0], ah[1], ah[2], ah[3], xh_b + aoff + ks * 32);
            ldm_x4(al[0], al[1], al[2], al[3], xl_b + aoff + ks * 32);
            #pragma unroll
            for (int j = 0; j < 4; ++j) {
                unsigned h0,h1,h2,h3, e0,e1,e2,e3;
                const unsigned off = boff + (j * 16 * TSTRIDE + ks * 8) * 4;
                ldm_x4(h0,h1,h2,h3, wh_b + off);
                ldm_x4(e0,e1,e2,e3, wl_b + off);
                mma_f16(o[2*j],   ah, h0, h1);
                mma_f16(o[2*j+1], ah, h2, h3);
                mma_f16(o[2*j],   ah, e0, e1);
                mma_f16(o[2*j+1], ah, e2, e3);
                mma_f16(o[2*j],   al, h0, h1);
                mma_f16(o[2*j+1], al, h2, h3);
            }
        }
    }

    if (mat < 2) {
        if (mat == 0) {
            #pragma unroll
            for (int sub = 0; sub < 8; ++sub)
                #pragma unroll
                for (int i = 0; i < 4; ++i) o[sub][i] *= LOG2E;
        }
        unsigned* dh = (mat == 0) ? g_qhi : g_khi;
        unsigned* dl = (mat == 0) ? g_qlo : g_klo;
        const int ra = row0 + g0 + g;
        #pragma unroll
        for (int sub = 0; sub < 8; ++sub) {
            unsigned h, l;
            split2h(o[sub][0], o[sub][1], h, l);
            dh[(size_t)ra * NPAIR + sub*4 + tig] = h;
            dl[(size_t)ra * NPAIR + sub*4 + tig] = l;
            split2h(o[sub][2], o[sub][3], h, l);
            dh[(size_t)(ra+8) * NPAIR + sub*4 + tig] = h;
            dl[(size_t)(ra+8) * NPAIR + sub*4 + tig] = l;
        }
    } else {
        // V: transpose via smem, emit single-fp16 [b][d][keypair]
        __syncthreads();
        float* smf = (float*)xs_hi;          // reuse: [64][68] floats
        const int rr = g0 + g;
        #pragma unroll
        for (int sub = 0; sub < 8; ++sub) {
            const int dc = sub * 8 + 2 * tig;
            smf[rr * 68 + dc]       = o[sub][0];
            smf[rr * 68 + dc + 1]   = o[sub][1];
            smf[(rr+8) * 68 + dc]   = o[sub][2];
            smf[(rr+8) * 68 + dc+1] = o[sub][3];
        }
        __syncthreads();
        const int b  = row0 / LL;
        const int lr = row0 % LL;
        const int d    = tid & 63;
        const int half = tid >> 6;
        #pragma unroll
        for (int i = 0; i < 16; ++i) {
            int kp = half * 16 + i;
            float v0 = smf[(2*kp)   * 68 + d];
            float v1 = smf[(2*kp+1) * 68 + d];
            size_t idx = (size_t)(b * AA + d) * (LL/2) + (lr >> 1) + kp;
            g_vthi[idx] = pack2h(v0, v1);
        }
    }
}

// ---------------------------------------------------------------------------
// Kernel 2: causal flash attention (fp16).  QK = 3-product split; P and V
// single fp16 -> PV = ONE product.  Q in SMEM; K/V double-buffered cp.async.
// grid = 320 (LPT), block = 256.  smem/CTA = 92160 B.
// ---------------------------------------------------------------------------
#define TILE_U32 (64 * TSTRIDE)
#define KVT_U32  (3 * TILE_U32)          // Kh, Kl, Vh per buffer
#define QOFF_U32 (2 * KVT_U32)           // Q region after 2 KV buffers
#define QARR_U32 (128 * TSTRIDE)         // 4608 per Q array

__global__ __launch_bounds__(256, 2)
void attn_kernel(float* __restrict__ out) {
    extern __shared__ unsigned smbuf[];
    const int gx = blockIdx.x;
    const int b  = gx & 3;
    const int jj = gx >> 2;              // 0..79, longest chunks first
    int qt2, chunk;
    if (jj < 32)      { qt2 = 24 + (jj >> 2);        chunk = jj & 3; }
    else if (jj < 56) { int t = jj - 32; qt2 = 16 + t / 3;    chunk = t % 3; }
    else if (jj < 72) { int t = jj - 56; qt2 = 8 + (t >> 1);  chunk = t & 1; }
    else              { qt2 = jj - 72;               chunk = 0; }

    const int q0    = qt2 * 128;
    const int tiles = 2 * qt2 + 2;
    const int kt0   = chunk * CHT;
    const int nt    = min(CHT, tiles - kt0);

    const int tid = threadIdx.x;
    const int lane = tid & 31;
    const int g   = lane >> 2;
    const int tig = lane & 3;
    const int g0  = (tid >> 5) * 16;

    const int crow = tid >> 2;
    const int ccol = (tid & 3) * 8;

    const unsigned smem_b = (unsigned)__cvta_generic_to_shared(smbuf);
    const unsigned boff   = bfrag_off(lane) * 4;
    const unsigned qh_b   = smem_b + QOFF_U32 * 4;
    const unsigned ql_b   = qh_b + QARR_U32 * 4;
    const unsigned aoff   = (g0 * TSTRIDE + afrag_off(lane)) * 4;

    // ---- stage Q tile (128 rows, hi+lo) into smem via cp.async ----
    {
        const int r   = tid >> 1;          // 0..127
        const int c0q = (tid & 1) * 16;
        const unsigned* sqh = &g_qhi[(size_t)(b*LL + q0 + r) * NPAIR + c0q];
        const unsigned* sql = &g_qlo[(size_t)(b*LL + q0 + r) * NPAIR + c0q];
        unsigned* dqh = smbuf + QOFF_U32 + r * TSTRIDE + c0q;
        unsigned* dql = smbuf + QOFF_U32 + QARR_U32 + r * TSTRIDE + c0q;
        #pragma unroll
        for (int i = 0; i < 4; ++i) {
            cpa16(dqh + 4*i, sqh + 4*i);
            cpa16(dql + 4*i, sql + 4*i);
        }
    }

    auto prefetch = [&](int bufsel, int k0) {
        unsigned* base = smbuf + bufsel * KVT_U32;
        unsigned* dkh = base              + crow * TSTRIDE + ccol;
        unsigned* dkl = base + 1*TILE_U32 + crow * TSTRIDE + ccol;
        unsigned* dvh = base + 2*TILE_U32 + crow * TSTRIDE + ccol;
        const unsigned* skh = &g_khi [(size_t)(b*LL + k0 + crow) * NPAIR + ccol];
        const unsigned* skl = &g_klo [(size_t)(b*LL + k0 + crow) * NPAIR + ccol];
        const unsigned* svh = &g_vthi[(size_t)(b*AA + crow) * (LL/2) + (k0 >> 1) + ccol];
        cpa16(dkh, skh); cpa16(dkh + 4, skh + 4);
        cpa16(dkl, skl); cpa16(dkl + 4, skl + 4);
        cpa16(dvh, svh); cpa16(dvh + 4, svh + 4);
        asm volatile("cp.async.commit_group;");
    };

    prefetch(0, kt0 * 64);   // group 0 = Q + first KV tile

    float o[8][4] = {};
    float m0 = -INFINITY, m1 = -INFINITY, l0 = 0.f, l1 = 0.f;

    for (int t = 0; t < nt; ++t) {
        const int kt = kt0 + t;
        asm volatile("cp.async.wait_group 0;");
        __syncthreads();
        if (t + 1 < nt) prefetch((t + 1) & 1, (kt + 1) * 64);

        const bool active = !(kt == 2*qt2 + 1 && g0 < 64);
        if (active) {
            const unsigned bufb = smem_b + ((t & 1) * KVT_U32) * 4;
            const unsigned kh_a = bufb + boff;
            const unsigned kl_a = kh_a + TILE_U32 * 4;
            const unsigned vh_a = kl_a + TILE_U32 * 4;

            float s[8][4];
            #pragma unroll
            for (int sub = 0; sub < 8; ++sub)
                #pragma unroll
                for (int i = 0; i < 4; ++i) s[sub][i] = 0.f;

            // ---- S = Q.K^T  (3-product fp16 split) ----
            #pragma unroll
            for (int ks = 0; ks < 4; ++ks) {
                unsigned ah[4], al[4];
                ldm_x4(ah[0], ah[1], ah[2], ah[3], qh_b + aoff + ks * 32);
                ldm_x4(al[0], al[1], al[2], al[3], ql_b + aoff + ks * 32);
                #pragma unroll
                for (int j = 0; j < 4; ++j) {
                    unsigned h0,h1,h2,h3, e0,e1,e2,e3;
                    const unsigned off = (j * 16 * TSTRIDE + ks * 8) * 4;
                    ldm_x4(h0,h1,h2,h3, kh_a + off);
                    ldm_x4(e0,e1,e2,e3, kl_a + off);
                    mma_f16(s[2*j],   ah, h0, h1);
                    mma_f16(s[2*j+1], ah, h2, h3);
                    mma_f16(s[2*j],   ah, e0, e1);
                    mma_f16(s[2*j+1], ah, e2, e3);
                    mma_f16(s[2*j],   al, h0, h1);
                    mma_f16(s[2*j+1], al, h2, h3);
                }
            }

            if (kt >= 2*qt2) {
                const int rel = (kt - 2*qt2) * 64;
                #pragma unroll
                for (int sub = 0; sub < 8; ++sub) {
                    const int kc = sub * 8 + 2 * tig + rel;
                    const int r_lo = g0 + g, r_hi = r_lo + 8;
                    if (kc     > r_lo) s[sub][0] = -INFINITY;
                    if (kc + 1 > r_lo) s[sub][1] = -INFINITY;
                    if (kc     > r_hi) s[sub][2] = -INFINITY;
                    if (kc + 1 > r_hi) s[sub][3] = -INFINITY;
                }
            }

            // ---- row max (quad reduce) ----
            float mt0 = -INFINITY, mt1 = -INFINITY;
            #pragma unroll
            for (int sub = 0; sub < 8; ++sub) {
                mt0 = fmaxf(mt0, fmaxf(s[sub][0], s[sub][1]));
                mt1 = fmaxf(mt1, fmaxf(s[sub][2], s[sub][3]));
            }
            mt0 = fmaxf(mt0, __shfl_xor_sync(0xffffffffu, mt0, 1));
            mt0 = fmaxf(mt0, __shfl_xor_sync(0xffffffffu, mt0, 2));
            mt1 = fmaxf(mt1, __shfl_xor_sync(0xffffffffu, mt1, 1));
            mt1 = fmaxf(mt1, __shfl_xor_sync(0xffffffffu, mt1, 2));

            const float mn0 = fmaxf(m0, mt0);
            const float mn1 = fmaxf(m1, mt1);
            const float c0f = ex2(m0 - mn0);   // log2 domain
            const float c1f = ex2(m1 - mn1);
            m0 = mn0; m1 = mn1;

            // rescale O once
            #pragma unroll
            for (int sub = 0; sub < 8; ++sub) {
                o[sub][0] *= c0f; o[sub][1] *= c0f;
                o[sub][2] *= c1f; o[sub][3] *= c1f;
            }

            // ---- exp + single-fp16 pack of P ----
            unsigned ph[8][2];
            float sum0 = 0.f, sum1 = 0.f;
            #pragma unroll
            for (int sub = 0; sub < 8; ++sub) {
                float p0 = ex2(s[sub][0] - mn0);
                float p1 = ex2(s[sub][1] - mn0);
                float p2 = ex2(s[sub][2] - mn1);
                float p3 = ex2(s[sub][3] - mn1);
                sum0 += p0 + p1;  sum1 += p2 + p3;
                ph[sub][0] = pack2h(p0, p1);
                ph[sub][1] = pack2h(p2, p3);
            }
            l0 = l0 * c0f + sum0;   // per-lane partials; quad-reduced at epilogue
            l1 = l1 * c1f + sum1;

            // ---- O += P.V  (ONE product: single-fp16 P and V) ----
            #pragma unroll
            for (int j = 0; j < 4; ++j) {       // key chunks
                unsigned a_[4] = {ph[2*j][0], ph[2*j][1], ph[2*j+1][0], ph[2*j+1][1]};
                #pragma unroll
                for (int dj = 0; dj < 4; ++dj) { // dim subpairs
                    unsigned h0,h1,h2,h3;
                    const unsigned off = (dj * 16 * TSTRIDE + j * 8) * 4;
                    ldm_x4(h0,h1,h2,h3, vh_a + off);
                    mma_f16(o[2*dj],   a_, h0, h1);
                    mma_f16(o[2*dj+1], a_, h2, h3);
                }
            }
        }
    }

    // ---- epilogue: reduce l across the quad, then write ----
    l0 += __shfl_xor_sync(0xffffffffu, l0, 1);
    l0 += __shfl_xor_sync(0xffffffffu, l0, 2);
    l1 += __shfl_xor_sync(0xffffffffu, l1, 1);
    l1 += __shfl_xor_sync(0xffffffffu, l1, 2);

    if (qt2 < 8) {
        const float inv0 = 1.f / l0;
        const float inv1 = 1.f / l1;
        float* base0 = out + ((size_t)(b * LL + q0 + g0 + g)) * AA;
        float* base1 = base0 + (size_t)8 * AA;
        #pragma unroll
        for (int sub = 0; sub < 8; ++sub) {
            const int dcol = sub * 8 + 2 * tig;
            *(float2*)&base0[dcol] = make_float2(o[sub][0] * inv0, o[sub][1] * inv0);
            *(float2*)&base1[dcol] = make_float2(o[sub][2] * inv1, o[sub][3] * inv1);
        }
    } else {
        const int slot = (b * NQT + qt2) * NCH + chunk;
        float* po = g_pO + (size_t)slot * 8192;
        #pragma unroll
        for (int sub = 0; sub < 8; ++sub) {
            const int dcol = sub * 8 + 2 * tig;
            *(float2*)&po[(g0 + g) * 64 + dcol]     = make_float2(o[sub][0], o[sub][1]);
            *(float2*)&po[(g0 + g + 8) * 64 + dcol] = make_float2(o[sub][2], o[sub][3]);
        }
        if (tig == 0) {
            g_pm[slot * 128 + g0 + g]     = m0;
            g_pm[slot * 128 + g0 + g + 8] = m1;
            g_pl[slot * 128 + g0 + g]     = l0;
            g_pl[slot * 128 + g0 + g + 8] = l1;
        }
    }
}

// ---------------------------------------------------------------------------
// Kernel 3: merge split-KV partials (qt2 >= 8).  grid = 384, block = 256.
// ---------------------------------------------------------------------------
__global__ __launch_bounds__(256)
void merge_kernel(float* __restrict__ out) {
    const int bqi     = blockIdx.x >> 2;
    const int quarter = blockIdx.x & 3;
    const int b   = bqi / 24;
    const int qt2 = 8 + bqi % 24;
    const int bq  = b * 32 + qt2;
    const int nch = (2 * qt2 + 17) >> 4;
    const int base_slot = bq * NCH;

    for (int e = threadIdx.x; e < 2048; e += 256) {
        const int row = quarter * 32 + (e >> 6);
        const int col = e & 63;
        float M = -INFINITY;
        #pragma unroll
        for (int c = 0; c < NCH; ++c)
            if (c < nch) M = fmaxf(M, g_pm[(base_slot + c) * 128 + row]);
        float denom = 0.f, acc = 0.f;
        #pragma unroll
        for (int c = 0; c < NCH; ++c) {
            if (c < nch) {
                float w = ex2(g_pm[(base_slot + c) * 128 + row] - M);
                denom += w * g_pl[(base_slot + c) * 128 + row];
                acc   += w * g_pO[(size_t)(base_slot + c) * 8192 + row * 64 + col];
            }
        }
        out[((size_t)(b * LL + qt2 * 128 + row)) * 64 + col] = acc / denom;
    }
}

// ---------------------------------------------------------------------------
extern "C" void kernel_launch(void* const* d_in, const int* in_sizes, int n_in,
                              void* d_out, int out_size) {
    (void)in_sizes; (void)n_in; (void)out_size;
    const float* x  = (const float*)d_in[0];
    const float* Wq = (const float*)d_in[1];
    const float* Wk = (const float*)d_in[2];
    const float* Wv = (const float*)d_in[3];
    float* out = (float*)d_out;

    prepw_kernel<<<32, 256>>>(Wq, Wk, Wv);
    {
        dim3 grid(3, NROWS / 64);
        qkv_kernel<<<grid, 128>>>(x);
    }
    {
        size_t smem = (size_t)(2 * KVT_U32 + 2 * QARR_U32) * sizeof(unsigned); // 92160 B
        cudaFuncSetAttribute(attn_kernel, cudaFuncAttributeMaxDynamicSharedMemorySize, (int)smem);
        attn_kernel<<<320, 256, smem>>>(out);
    }
    merge_kernel<<<384, 256>>>(out);
}